// round 14
// baseline (speedup 1.0000x reference)
#include <cuda_runtime.h>
#include <cuda_bf16.h>
#include <cstdint>

// Problem dims
#define Bb  64
#define Tt  512
#define Hh  1024
#define INn 1024
#define BT  32768   // Bb*Tt
#define BH  65536   // Bb*Hh

// ---------------- static device scratch -------------------------------------
__device__ __nv_bfloat16 g_xh[(size_t)BT * INn];       // x hi  (64 MB)
__device__ __nv_bfloat16 g_xl[(size_t)BT * INn];       // x lo  (64 MB)
__device__ __nv_bfloat16 g_wh[4ull * Hh * INn];        // proj W hi (f,i,o,c)
__device__ __nv_bfloat16 g_wl[4ull * Hh * INn];        // proj W lo
__device__ __nv_bfloat16 g_rwh[3ull * Hh * Hh];        // rec W hi (f,i,o)
__device__ __nv_bfloat16 g_rwl[3ull * Hh * Hh];        // rec W lo
__device__ float         g_bias[4 * Hh];               // bcf,bci,bco,bxc
__device__ float         g_P[4ull * Tt * Bb * Hh];     // preacts [g][t][b][h] (512 MB)
// ct in MMA A-fragment layout, double buffered:
// [phase][bt(4)][kt(64)][lane(32)][8 uints: ah0..ah3, al0..al3]
__device__ unsigned      g_ctF[2][65536];
__device__ unsigned      g_bar[640];                   // grid-barrier counters

// ---------------- helpers ----------------
__device__ __forceinline__ float sigf(float v) { return 1.0f / (1.0f + __expf(-v)); }

__device__ __forceinline__ void mma_bf16(float c[4], const unsigned a[4], const unsigned b[2]) {
    asm volatile(
        "mma.sync.aligned.m16n8k16.row.col.f32.bf16.bf16.f32 "
        "{%0,%1,%2,%3},{%4,%5,%6,%7},{%8,%9},{%0,%1,%2,%3};\n"
        : "+f"(c[0]), "+f"(c[1]), "+f"(c[2]), "+f"(c[3])
        : "r"(a[0]), "r"(a[1]), "r"(a[2]), "r"(a[3]), "r"(b[0]), "r"(b[1]));
}

__device__ __forceinline__ void cp16(void* dst, const void* src) {
    unsigned d = (unsigned)__cvta_generic_to_shared(dst);
    asm volatile("cp.async.cg.shared.global [%0], [%1], 16;\n" :: "r"(d), "l"(src));
}
__device__ __forceinline__ void cp_commit() { asm volatile("cp.async.commit_group;\n"); }
__device__ __forceinline__ void cp_wait1()  { asm volatile("cp.async.wait_group 1;\n"); }
__device__ __forceinline__ void cp_wait0()  { asm volatile("cp.async.wait_group 0;\n"); }

__device__ __forceinline__ void grid_barrier(int slot) {
    __syncthreads();
    if (threadIdx.x == 0) {
        __threadfence();
        unsigned n = gridDim.x;
        if (atomicAdd(&g_bar[slot], 1u) + 1u < n) {
            while (*(volatile unsigned*)&g_bar[slot] < n) __nanosleep(32);
        }
        __threadfence();
    }
    __syncthreads();
}

// ---------------- setup kernels ----------------
__global__ void k_init() {
    if (threadIdx.x < 640) g_bar[threadIdx.x] = 0u;
}

__global__ void k_split_x(const float* __restrict__ x) {
    const size_t n4 = (size_t)BT * INn / 4;
    const size_t stride = (size_t)gridDim.x * blockDim.x;
    for (size_t i = (size_t)blockIdx.x * blockDim.x + threadIdx.x; i < n4; i += stride) {
        float4 v = ((const float4*)x)[i];
        __nv_bfloat16 h0 = __float2bfloat16(v.x), h1 = __float2bfloat16(v.y);
        __nv_bfloat16 h2 = __float2bfloat16(v.z), h3 = __float2bfloat16(v.w);
        __nv_bfloat16 l0 = __float2bfloat16(v.x - __bfloat162float(h0));
        __nv_bfloat16 l1 = __float2bfloat16(v.y - __bfloat162float(h1));
        __nv_bfloat16 l2 = __float2bfloat16(v.z - __bfloat162float(h2));
        __nv_bfloat16 l3 = __float2bfloat16(v.w - __bfloat162float(h3));
        ((ushort4*)g_xh)[i] = make_ushort4(__bfloat16_as_ushort(h0), __bfloat16_as_ushort(h1),
                                           __bfloat16_as_ushort(h2), __bfloat16_as_ushort(h3));
        ((ushort4*)g_xl)[i] = make_ushort4(__bfloat16_as_ushort(l0), __bfloat16_as_ushort(l1),
                                           __bfloat16_as_ushort(l2), __bfloat16_as_ushort(l3));
    }
}

__global__ void k_split_w(const float* __restrict__ src, int sel, size_t off, size_t n4) {
    __nv_bfloat16* dh = sel ? g_rwh : g_wh;
    __nv_bfloat16* dl = sel ? g_rwl : g_wl;
    const size_t stride = (size_t)gridDim.x * blockDim.x;
    for (size_t i = (size_t)blockIdx.x * blockDim.x + threadIdx.x; i < n4; i += stride) {
        float4 v = ((const float4*)src)[i];
        __nv_bfloat16 h0 = __float2bfloat16(v.x), h1 = __float2bfloat16(v.y);
        __nv_bfloat16 h2 = __float2bfloat16(v.z), h3 = __float2bfloat16(v.w);
        __nv_bfloat16 l0 = __float2bfloat16(v.x - __bfloat162float(h0));
        __nv_bfloat16 l1 = __float2bfloat16(v.y - __bfloat162float(h1));
        __nv_bfloat16 l2 = __float2bfloat16(v.z - __bfloat162float(h2));
        __nv_bfloat16 l3 = __float2bfloat16(v.w - __bfloat162float(h3));
        ((ushort4*)(dh + off))[i] = make_ushort4(__bfloat16_as_ushort(h0), __bfloat16_as_ushort(h1),
                                                 __bfloat16_as_ushort(h2), __bfloat16_as_ushort(h3));
        ((ushort4*)(dl + off))[i] = make_ushort4(__bfloat16_as_ushort(l0), __bfloat16_as_ushort(l1),
                                                 __bfloat16_as_ushort(l2), __bfloat16_as_ushort(l3));
    }
}

__global__ void k_bias(const float* __restrict__ bf, const float* __restrict__ bi,
                       const float* __restrict__ bo, const float* __restrict__ bc) {
    int i = blockIdx.x * blockDim.x + threadIdx.x;
    if (i < Hh) {
        g_bias[i]          = bf[i];
        g_bias[Hh + i]     = bi[i];
        g_bias[2 * Hh + i] = bo[i];
        g_bias[3 * Hh + i] = bc[i];
    }
}

// ---------------- projection GEMM with cp.async 3-stage pipeline ------------
// C tile 128x128, 8 warps (2x4), warp tile 64x32, K-chunk 32 halves.
// Stage layout (40,960 B): Ah | Al | Bh | Bl, each 128 rows x 80 B (40-half pad).
#define PSTAGE 40960
#define PARR   10240

__global__ void __launch_bounds__(256) k_proj() {
    extern __shared__ char dsm[];
    const int bn = blockIdx.x;              // 0..31  N tiles (fastest -> A L2 reuse)
    const int bm = blockIdx.y;              // 0..255 M tiles
    const int tid = threadIdx.x;
    const int wid = tid >> 5, lane = tid & 31;
    const int wm = wid >> 2, wn = wid & 3;
    const int grp = lane >> 2, tg = lane & 3;

    const unsigned* gsrc[4] = {(const unsigned*)g_xh, (const unsigned*)g_xl,
                               (const unsigned*)g_wh, (const unsigned*)g_wl};

    float acc[4][4][4];
#pragma unroll
    for (int mt = 0; mt < 4; ++mt)
#pragma unroll
        for (int nt = 0; nt < 4; ++nt)
#pragma unroll
            for (int r = 0; r < 4; ++r) acc[mt][nt][r] = 0.f;

    // issue one k-chunk into stage kc%3
    auto issue = [&](int kc) {
        char* st = dsm + (kc % 3) * PSTAGE;
#pragma unroll
        for (int i = 0; i < 8; ++i) {
            const int a = i >> 1;
            int row = (i & 1) * 64 + (tid >> 2);
            int c16 = tid & 3;
            char* dst = st + a * PARR + row * 80 + c16 * 16;
            int rglob = ((a < 2) ? bm : bn) * 128 + row;
            const unsigned* src = gsrc[a] + (size_t)rglob * 512 + kc * 16 + c16 * 4;
            cp16(dst, src);
        }
        cp_commit();
    };

    issue(0);
    issue(1);

    for (int kc = 0; kc < 32; ++kc) {
        if (kc < 31) cp_wait1(); else cp_wait0();
        __syncthreads();
        if (kc + 2 < 32) issue(kc + 2);

        const char* st = dsm + (kc % 3) * PSTAGE;
        const __nv_bfloat16* sAh = (const __nv_bfloat16*)(st);
        const __nv_bfloat16* sAl = (const __nv_bfloat16*)(st + PARR);
        const __nv_bfloat16* sBh = (const __nv_bfloat16*)(st + 2 * PARR);
        const __nv_bfloat16* sBl = (const __nv_bfloat16*)(st + 3 * PARR);

#pragma unroll
        for (int kk = 0; kk < 2; ++kk) {
            unsigned ah[4][4], al[4][4], bhf[4][2], blf[4][2];
            const int c0 = kk * 16 + tg * 2;
#pragma unroll
            for (int mt = 0; mt < 4; ++mt) {
                int r0 = wm * 64 + mt * 16 + grp;
                ah[mt][0] = *(const unsigned*)&sAh[r0 * 40 + c0];
                ah[mt][1] = *(const unsigned*)&sAh[(r0 + 8) * 40 + c0];
                ah[mt][2] = *(const unsigned*)&sAh[r0 * 40 + c0 + 8];
                ah[mt][3] = *(const unsigned*)&sAh[(r0 + 8) * 40 + c0 + 8];
                al[mt][0] = *(const unsigned*)&sAl[r0 * 40 + c0];
                al[mt][1] = *(const unsigned*)&sAl[(r0 + 8) * 40 + c0];
                al[mt][2] = *(const unsigned*)&sAl[r0 * 40 + c0 + 8];
                al[mt][3] = *(const unsigned*)&sAl[(r0 + 8) * 40 + c0 + 8];
            }
#pragma unroll
            for (int nt = 0; nt < 4; ++nt) {
                int br = wn * 32 + nt * 8 + grp;
                bhf[nt][0] = *(const unsigned*)&sBh[br * 40 + c0];
                bhf[nt][1] = *(const unsigned*)&sBh[br * 40 + c0 + 8];
                blf[nt][0] = *(const unsigned*)&sBl[br * 40 + c0];
                blf[nt][1] = *(const unsigned*)&sBl[br * 40 + c0 + 8];
            }
#pragma unroll
            for (int mt = 0; mt < 4; ++mt)
#pragma unroll
                for (int nt = 0; nt < 4; ++nt) {
                    mma_bf16(acc[mt][nt], ah[mt], bhf[nt]);
                    mma_bf16(acc[mt][nt], ah[mt], blf[nt]);
                    mma_bf16(acc[mt][nt], al[mt], bhf[nt]);
                }
        }
        __syncthreads();
    }

    // epilogue: scatter into [gate][t][b][h] (+bias)
#pragma unroll
    for (int mt = 0; mt < 4; ++mt) {
#pragma unroll
        for (int nt = 0; nt < 4; ++nt) {
            int m0 = bm * 128 + wm * 64 + mt * 16 + grp;
            int n0 = bn * 128 + wn * 32 + nt * 8 + tg * 2;
            int g = n0 >> 10, h = n0 & 1023;
            float b0 = g_bias[n0], b1 = g_bias[n0 + 1];
#pragma unroll
            for (int e = 0; e < 2; ++e) {
                int m = m0 + 8 * e;
                int b = m >> 9, t = m & 511;
                size_t idx = (((size_t)g * Tt + t) * Bb + b) * Hh + h;
                float2 v;
                v.x = acc[mt][nt][2 * e] + b0;
                v.y = acc[mt][nt][2 * e + 1] + b1;
                *(float2*)&g_P[idx] = v;
            }
        }
    }
}

// ---------------- persistent recurrence kernel ------------------------------
// 128 CTAs x 128 threads. CTA j owns h in [8j,8j+8), gates f,i,o (N=3x8).
// Rec weights pre-permuted into B-frag layout in smem (96 KB) once.
// ct kept in fp32 registers; bf16 hi/lo copy stored in A-frag layout in L2.
__global__ void __launch_bounds__(128) k_rec(const float* __restrict__ c0,
                                             float* __restrict__ out_h,
                                             float* __restrict__ out_last) {
    extern __shared__ unsigned sWf[];   // [nt(3)][kt(64)][lane(32)][4: bh0,bh1,bl0,bl1]

    const int j = blockIdx.x;
    const int tid = threadIdx.x, wid = tid >> 5, lane = tid & 31;
    const int grp = lane >> 2, tg = lane & 3;
    const int h0 = j * 8;

    // fill weight frags (one-time)
    for (int idx = tid; idx < 24576; idx += 128) {
        int reg = idx & 3, l = (idx >> 2) & 31, kt = (idx >> 7) & 63, nt = idx >> 13;
        const unsigned* src = (reg < 2) ? (const unsigned*)g_rwh : (const unsigned*)g_rwl;
        int col = kt * 8 + (l & 3) + (reg & 1) * 4;
        sWf[idx] = src[(size_t)(nt * Hh + h0 + (l >> 2)) * 512 + col];
    }

    const int brow = wid * 16 + grp;       // base batch row (bt = wid)
    float creg[4];
    {
        float z0 = c0[h0 + tg * 2], z1 = c0[h0 + tg * 2 + 1];
        creg[0] = z0; creg[1] = z1; creg[2] = z0; creg[3] = z1;
        // write phase-0 ct fragments
        const size_t wr = ((size_t)(wid * 64 + (j >> 1)) * 32 + lane) * 8 + (j & 1) * 2;
#pragma unroll
        for (int hl = 0; hl < 2; ++hl) {   // 0=hi, 1=lo
            uint2 v;
#pragma unroll
            for (int e = 0; e < 2; ++e) {
                float a0 = creg[2 * e], a1 = creg[2 * e + 1];
                __nv_bfloat16 x0 = __float2bfloat16(a0), x1 = __float2bfloat16(a1);
                if (hl) {
                    x0 = __float2bfloat16(a0 - __bfloat162float(x0));
                    x1 = __float2bfloat16(a1 - __bfloat162float(x1));
                }
                unsigned pv = (unsigned)__bfloat16_as_ushort(x0) |
                              ((unsigned)__bfloat16_as_ushort(x1) << 16);
                if (e == 0) v.x = pv; else v.y = pv;
            }
            __stcg((uint2*)&g_ctF[0][wr + 4 * hl], v);
        }
    }
    __syncthreads();
    grid_barrier(0);

    const size_t GST = (size_t)Tt * Bb * Hh;   // gate stride in g_P

    for (int t = 0; t < Tt; ++t) {
        const int p = t & 1;
        const uint4* A = (const uint4*)g_ctF[p];

        // prefetch this step's preacts (independent of ct / barrier)
        size_t p0 = ((size_t)t * Bb + brow) * Hh + h0 + tg * 2;
        size_t p1 = p0 + 8 * Hh;
        float2 Pf0 = *(const float2*)&g_P[p0],           Pf1 = *(const float2*)&g_P[p1];
        float2 Pi0 = *(const float2*)&g_P[p0 + GST],     Pi1 = *(const float2*)&g_P[p1 + GST];
        float2 Po0 = *(const float2*)&g_P[p0 + 2 * GST], Po1 = *(const float2*)&g_P[p1 + 2 * GST];
        float2 Pc0 = *(const float2*)&g_P[p0 + 3 * GST], Pc1 = *(const float2*)&g_P[p1 + 3 * GST];

        float acc[3][4];
#pragma unroll
        for (int nt = 0; nt < 3; ++nt) { acc[nt][0] = acc[nt][1] = acc[nt][2] = acc[nt][3] = 0.f; }

#pragma unroll 8
        for (int kt = 0; kt < 64; ++kt) {
            const size_t ab = ((size_t)(wid * 64 + kt) * 32 + lane) * 2;   // uint4 units
            uint4 ahv = __ldcg(&A[ab]);
            uint4 alv = __ldcg(&A[ab + 1]);
#pragma unroll
            for (int nt = 0; nt < 3; ++nt) {
                uint4 bb = *(const uint4*)&sWf[((nt * 64 + kt) * 32 + lane) * 4];
                unsigned bh[2] = {bb.x, bb.y};
                unsigned bl[2] = {bb.z, bb.w};
                mma_bf16(acc[nt], (const unsigned*)&ahv, bh);
                mma_bf16(acc[nt], (const unsigned*)&ahv, bl);
                mma_bf16(acc[nt], (const unsigned*)&alv, bh);
            }
        }

        // elementwise update + write next-phase ct fragments
        const int pn = p ^ 1;
        const size_t wr = ((size_t)(wid * 64 + (j >> 1)) * 32 + lane) * 8 + (j & 1) * 2;
        uint2 vh, vl;
#pragma unroll
        for (int e = 0; e < 2; ++e) {
            int b = brow + 8 * e;
            float2 Pf = e ? Pf1 : Pf0, Pi = e ? Pi1 : Pi0;
            float2 Po = e ? Po1 : Po0, Pc = e ? Pc1 : Pc0;
            float f0 = sigf(acc[0][2 * e] + Pf.x);
            float f1 = sigf(acc[0][2 * e + 1] + Pf.y);
            float i0 = sigf(acc[1][2 * e] + Pi.x);
            float i1 = sigf(acc[1][2 * e + 1] + Pi.y);
            float o0 = sigf(acc[2][2 * e] + Po.x);
            float o1 = sigf(acc[2][2 * e + 1] + Po.y);
            float c0n = f0 * creg[2 * e] + i0 * tanhf(Pc.x);
            float c1n = f1 * creg[2 * e + 1] + i1 * tanhf(Pc.y);
            creg[2 * e] = c0n; creg[2 * e + 1] = c1n;

            __nv_bfloat16 ch0 = __float2bfloat16(c0n), ch1 = __float2bfloat16(c1n);
            __nv_bfloat16 cl0 = __float2bfloat16(c0n - __bfloat162float(ch0));
            __nv_bfloat16 cl1 = __float2bfloat16(c1n - __bfloat162float(ch1));
            unsigned hv = (unsigned)__bfloat16_as_ushort(ch0) | ((unsigned)__bfloat16_as_ushort(ch1) << 16);
            unsigned lv = (unsigned)__bfloat16_as_ushort(cl0) | ((unsigned)__bfloat16_as_ushort(cl1) << 16);
            if (e == 0) { vh.x = hv; vl.x = lv; } else { vh.y = hv; vl.y = lv; }

            float2 hv2;
            hv2.x = o0 * tanhf(c0n);
            hv2.y = o1 * tanhf(c1n);
            *(float2*)&out_h[((size_t)b * Tt + t) * Hh + h0 + tg * 2] = hv2;
            if (out_last != nullptr && t == Tt - 1) {
                *(float2*)&out_last[(size_t)b * Hh + h0 + tg * 2] = hv2;
            }
        }
        __stcg((uint2*)&g_ctF[pn][wr], vh);
        __stcg((uint2*)&g_ctF[pn][wr + 4], vl);

        grid_barrier(t + 1);
    }
}

// ---------------- launch ----------------------------------------------------
extern "C" void kernel_launch(void* const* d_in, const int* in_sizes, int n_in,
                              void* d_out, int out_size) {
    const float* x   = (const float*)d_in[0];
    const float* Wxf = (const float*)d_in[1];
    const float* Wcf = (const float*)d_in[2];
    const float* bcf = (const float*)d_in[3];
    const float* Wxi = (const float*)d_in[4];
    const float* Wci = (const float*)d_in[5];
    const float* bci = (const float*)d_in[6];
    const float* Wxo = (const float*)d_in[7];
    const float* Wco = (const float*)d_in[8];
    const float* bco = (const float*)d_in[9];
    const float* Wxc = (const float*)d_in[10];
    const float* bxc = (const float*)d_in[11];
    const float* c0  = (const float*)d_in[12];
    float* out = (float*)d_out;

    const long long hid_elems = (long long)Bb * Tt * Hh;
    float* out_last = ((long long)out_size >= hid_elems + (long long)Bb * Hh)
                          ? out + hid_elems : nullptr;

    const int proj_smem = 3 * PSTAGE;        // 122,880 B
    const int rec_smem  = 24576 * 4;         // 98,304 B
    cudaFuncSetAttribute(k_proj, cudaFuncAttributeMaxDynamicSharedMemorySize, proj_smem);
    cudaFuncSetAttribute(k_rec,  cudaFuncAttributeMaxDynamicSharedMemorySize, rec_smem);

    k_init<<<1, 640>>>();
    k_split_x<<<2048, 256>>>(x);
    const size_t MW4 = (size_t)Hh * INn / 4;
    k_split_w<<<512, 256>>>(Wxf, 0, 0,                     MW4);
    k_split_w<<<512, 256>>>(Wxi, 0, (size_t)1 * Hh * INn,  MW4);
    k_split_w<<<512, 256>>>(Wxo, 0, (size_t)2 * Hh * INn,  MW4);
    k_split_w<<<512, 256>>>(Wxc, 0, (size_t)3 * Hh * INn,  MW4);
    k_split_w<<<512, 256>>>(Wcf, 1, 0,                     MW4);
    k_split_w<<<512, 256>>>(Wci, 1, (size_t)1 * Hh * Hh,   MW4);
    k_split_w<<<512, 256>>>(Wco, 1, (size_t)2 * Hh * Hh,   MW4);
    k_bias<<<4, 256>>>(bcf, bci, bco, bxc);
    k_proj<<<dim3(32, 256), 256, proj_smem>>>();
    k_rec<<<128, 128, rec_smem>>>(c0, out, out_last);
}

// round 16
// speedup vs baseline: 2.3793x; 2.3793x over previous
#include <cuda_runtime.h>
#include <cuda_fp16.h>
#include <cstdint>

// Problem dims
#define Bb  64
#define Tt  512
#define Hh  1024
#define INn 1024
#define BT  32768   // Bb*Tt
#define BH  65536   // Bb*Hh

// ---------------- static device scratch -------------------------------------
__device__ __half  g_x  [(size_t)BT * INn];        // x fp16 (64 MB)
__device__ __half  g_wh [4ull * Hh * INn];         // proj W hi (f,i,o,c)
__device__ __half  g_wl [4ull * Hh * INn];         // proj W lo
__device__ __half  g_rwh[3ull * Hh * Hh];          // rec W hi (f,i,o)
__device__ __half  g_rwl[3ull * Hh * Hh];          // rec W lo
__device__ float   g_bias[4 * Hh];                 // bcf,bci,bco,bxc
__device__ float   g_P[4ull * Tt * Bb * Hh];       // preacts [g][t][b][h] (512 MB)
// ct (fp16, single) in mma A-fragment layout, double buffered:
// [phase][bt(4)][kt(64)][lane(32)][4 uints: a0..a3]
__device__ unsigned g_ctF[2][32768];
__device__ unsigned g_bar[640];                    // grid-barrier counters

// ---------------- helpers ----------------
__device__ __forceinline__ float sigf(float v) { return 1.0f / (1.0f + __expf(-v)); }

// fast, inf-safe tanh
__device__ __forceinline__ float tanhf_fast(float x) {
    float ax = fabsf(x);
    float e = __expf(2.0f * ax);        // large ax -> inf -> 2/inf = 0 -> r = 1
    float r = 1.0f - 2.0f / (e + 1.0f);
    return copysignf(r, x);
}

// D += A*B, m16n8k16 row.col, fp16 in / fp32 acc
__device__ __forceinline__ void mma_f16(float c[4], const unsigned a[4], const unsigned b[2]) {
    asm volatile(
        "mma.sync.aligned.m16n8k16.row.col.f32.f16.f16.f32 "
        "{%0,%1,%2,%3},{%4,%5,%6,%7},{%8,%9},{%0,%1,%2,%3};\n"
        : "+f"(c[0]), "+f"(c[1]), "+f"(c[2]), "+f"(c[3])
        : "r"(a[0]), "r"(a[1]), "r"(a[2]), "r"(a[3]), "r"(b[0]), "r"(b[1]));
}

__device__ __forceinline__ void cp16(void* dst, const void* src) {
    unsigned d = (unsigned)__cvta_generic_to_shared(dst);
    asm volatile("cp.async.cg.shared.global [%0], [%1], 16;\n" :: "r"(d), "l"(src));
}
__device__ __forceinline__ void cp_commit() { asm volatile("cp.async.commit_group;\n"); }
__device__ __forceinline__ void cp_wait1()  { asm volatile("cp.async.wait_group 1;\n"); }
__device__ __forceinline__ void cp_wait0()  { asm volatile("cp.async.wait_group 0;\n"); }

__device__ __forceinline__ unsigned pack2h(float a, float b) {
    __half ha = __float2half_rn(a), hb = __float2half_rn(b);
    return (unsigned)__half_as_ushort(ha) | ((unsigned)__half_as_ushort(hb) << 16);
}

__device__ __forceinline__ void grid_barrier(int slot) {
    __syncthreads();
    if (threadIdx.x == 0) {
        __threadfence();
        unsigned n = gridDim.x;
        if (atomicAdd(&g_bar[slot], 1u) + 1u < n) {
            while (*(volatile unsigned*)&g_bar[slot] < n) { }
        }
        __threadfence();
    }
    __syncthreads();
}

// ---------------- setup kernels ----------------
__global__ void k_init() {
    if (threadIdx.x < 640) g_bar[threadIdx.x] = 0u;
}

__global__ void k_split_x(const float* __restrict__ x) {
    const size_t n4 = (size_t)BT * INn / 4;
    const size_t stride = (size_t)gridDim.x * blockDim.x;
    for (size_t i = (size_t)blockIdx.x * blockDim.x + threadIdx.x; i < n4; i += stride) {
        float4 v = ((const float4*)x)[i];
        ushort4 o;
        o.x = __half_as_ushort(__float2half_rn(v.x));
        o.y = __half_as_ushort(__float2half_rn(v.y));
        o.z = __half_as_ushort(__float2half_rn(v.z));
        o.w = __half_as_ushort(__float2half_rn(v.w));
        ((ushort4*)g_x)[i] = o;
    }
}

// All 7 weight hi/lo splits in ONE launch (keeps launch count at 6 so ncu -s 5
// captures k_rec). y = 0..3 -> proj Wx{f,i,o,c}; y = 4..6 -> rec Wc{f,i,o}.
__global__ void k_split_all(const float* s0, const float* s1, const float* s2,
                            const float* s3, const float* s4, const float* s5,
                            const float* s6) {
    const float* srcs[7] = {s0, s1, s2, s3, s4, s5, s6};
    const int y = blockIdx.y;
    const float* __restrict__ src = srcs[y];
    __half* dh = (y < 4) ? g_wh : g_rwh;
    __half* dl = (y < 4) ? g_wl : g_rwl;
    const size_t off = ((y < 4) ? (size_t)y : (size_t)(y - 4)) * Hh * INn;
    const size_t n4 = (size_t)Hh * INn / 4;
    const size_t stride = (size_t)gridDim.x * blockDim.x;
    for (size_t i = (size_t)blockIdx.x * blockDim.x + threadIdx.x; i < n4; i += stride) {
        float4 v = ((const float4*)src)[i];
        __half h0 = __float2half_rn(v.x), h1 = __float2half_rn(v.y);
        __half h2 = __float2half_rn(v.z), h3 = __float2half_rn(v.w);
        __half l0 = __float2half_rn(v.x - __half2float(h0));
        __half l1 = __float2half_rn(v.y - __half2float(h1));
        __half l2 = __float2half_rn(v.z - __half2float(h2));
        __half l3 = __float2half_rn(v.w - __half2float(h3));
        ((ushort4*)(dh + off))[i] = make_ushort4(__half_as_ushort(h0), __half_as_ushort(h1),
                                                 __half_as_ushort(h2), __half_as_ushort(h3));
        ((ushort4*)(dl + off))[i] = make_ushort4(__half_as_ushort(l0), __half_as_ushort(l1),
                                                 __half_as_ushort(l2), __half_as_ushort(l3));
    }
}

__global__ void k_bias(const float* __restrict__ bf, const float* __restrict__ bi,
                       const float* __restrict__ bo, const float* __restrict__ bc) {
    int i = blockIdx.x * blockDim.x + threadIdx.x;
    if (i < Hh) {
        g_bias[i]          = bf[i];
        g_bias[Hh + i]     = bi[i];
        g_bias[2 * Hh + i] = bo[i];
        g_bias[3 * Hh + i] = bc[i];
    }
}

// ---------------- projection GEMM: P = x @ Wx^T + bias (fp16 2-product) -----
// C tile 128x128, 8 warps (2x4), warp tile 64x32, K-chunk 32 halves.
// Stage (30,720 B): A(x) | Bh | Bl, each 128 rows x 80 B (40-half pad). 3 stages.
#define PARR   10240
#define PSTAGE (3 * PARR)

__global__ void __launch_bounds__(256) k_proj() {
    extern __shared__ char dsm[];
    const int bn = blockIdx.x;              // 0..31  N tiles (fastest -> x reuse in L2)
    const int bm = blockIdx.y;              // 0..255 M tiles
    const int tid = threadIdx.x;
    const int wid = tid >> 5, lane = tid & 31;
    const int wm = wid >> 2, wn = wid & 3;
    const int grp = lane >> 2, tg = lane & 3;

    float acc[4][4][4];
#pragma unroll
    for (int mt = 0; mt < 4; ++mt)
#pragma unroll
        for (int nt = 0; nt < 4; ++nt)
#pragma unroll
            for (int r = 0; r < 4; ++r) acc[mt][nt][r] = 0.f;

    // load one K-chunk (32 halves) into stage kc%3: 3 arrays x 128 rows x 64 B
    auto issue = [&](int kc) {
        char* st = dsm + (kc % 3) * PSTAGE;
#pragma unroll
        for (int i = 0; i < 6; ++i) {
            int flat = tid + i * 256;            // 0..1535
            int arr = flat >> 9;                 // 0..2
            int rem = flat & 511;
            int row = rem >> 2, c16 = rem & 3;   // row 0..127, 16B-chunk 0..3
            char* dst = st + arr * PARR + row * 80 + c16 * 16;
            const __half* src;
            if (arr == 0)
                src = g_x  + (size_t)(bm * 128 + row) * 1024 + kc * 32 + c16 * 8;
            else if (arr == 1)
                src = g_wh + (size_t)(bn * 128 + row) * 1024 + kc * 32 + c16 * 8;
            else
                src = g_wl + (size_t)(bn * 128 + row) * 1024 + kc * 32 + c16 * 8;
            cp16(dst, src);
        }
        cp_commit();
    };

    issue(0);
    issue(1);

    for (int kc = 0; kc < 32; ++kc) {
        if (kc < 31) cp_wait1(); else cp_wait0();
        __syncthreads();
        if (kc + 2 < 32) issue(kc + 2);

        const char* st = dsm + (kc % 3) * PSTAGE;
        const __half* sA  = (const __half*)(st);
        const __half* sBh = (const __half*)(st + PARR);
        const __half* sBl = (const __half*)(st + 2 * PARR);

#pragma unroll
        for (int kk = 0; kk < 2; ++kk) {
            unsigned a[4][4], bh[4][2], bl[4][2];
            const int c0 = kk * 16 + tg * 2;
#pragma unroll
            for (int mt = 0; mt < 4; ++mt) {
                int r0 = wm * 64 + mt * 16 + grp;
                a[mt][0] = *(const unsigned*)&sA[r0 * 40 + c0];
                a[mt][1] = *(const unsigned*)&sA[(r0 + 8) * 40 + c0];
                a[mt][2] = *(const unsigned*)&sA[r0 * 40 + c0 + 8];
                a[mt][3] = *(const unsigned*)&sA[(r0 + 8) * 40 + c0 + 8];
            }
#pragma unroll
            for (int nt = 0; nt < 4; ++nt) {
                int br = wn * 32 + nt * 8 + grp;
                bh[nt][0] = *(const unsigned*)&sBh[br * 40 + c0];
                bh[nt][1] = *(const unsigned*)&sBh[br * 40 + c0 + 8];
                bl[nt][0] = *(const unsigned*)&sBl[br * 40 + c0];
                bl[nt][1] = *(const unsigned*)&sBl[br * 40 + c0 + 8];
            }
#pragma unroll
            for (int mt = 0; mt < 4; ++mt)
#pragma unroll
                for (int nt = 0; nt < 4; ++nt) {
                    mma_f16(acc[mt][nt], a[mt], bh[nt]);
                    mma_f16(acc[mt][nt], a[mt], bl[nt]);
                }
        }
        __syncthreads();
    }

    // epilogue: scatter into [gate][t][b][h] (+bias)
#pragma unroll
    for (int mt = 0; mt < 4; ++mt) {
#pragma unroll
        for (int nt = 0; nt < 4; ++nt) {
            int m0 = bm * 128 + wm * 64 + mt * 16 + grp;
            int n0 = bn * 128 + wn * 32 + nt * 8 + tg * 2;
            int g = n0 >> 10, h = n0 & 1023;
            float b0 = g_bias[n0], b1 = g_bias[n0 + 1];
#pragma unroll
            for (int e = 0; e < 2; ++e) {
                int m = m0 + 8 * e;
                int b = m >> 9, t = m & 511;
                size_t idx = (((size_t)g * Tt + t) * Bb + b) * Hh + h;
                float2 v;
                v.x = acc[mt][nt][2 * e] + b0;
                v.y = acc[mt][nt][2 * e + 1] + b1;
                *(float2*)&g_P[idx] = v;
            }
        }
    }
}

// ---------------- persistent recurrence kernel ------------------------------
// 128 CTAs x 256 threads. CTA j owns h in [8j,8j+8), gates f,i,o (N=3x8).
// Warp = (bt 0..3, khalf 0..1). khalf0: kt 0..31, khalf1: kt 32..63.
// Partials reduced through smem; khalf0 warps do the elementwise update.
// ct: fp32 in regs; fp16 single-rounded copy in A-frag layout in L2.
#define RED_STRIDE 13
__global__ void __launch_bounds__(256) k_rec(const float* __restrict__ c0,
                                             float* __restrict__ out_h,
                                             float* __restrict__ out_last) {
    extern __shared__ __align__(16) unsigned sWf[];   // [nt(3)][kt(64)][lane(32)][4: bh0,bh1,bl0,bl1]
    float* sRed = (float*)(sWf + 24576);              // [4][32][RED_STRIDE]

    const int j = blockIdx.x;
    const int tid = threadIdx.x, wid = tid >> 5, lane = tid & 31;
    const int grp = lane >> 2, tg = lane & 3;
    const int bt = wid & 3;                // batch-tile
    const int kh = wid >> 2;               // k-half
    const int kth = kh * 32;
    const int h0 = j * 8;

    // one-time: rec weights into B-frag layout (fp16 hi/lo)
    for (int idx = tid; idx < 24576; idx += 256) {
        int reg = idx & 3, l = (idx >> 2) & 31, kt = (idx >> 7) & 63, nt = idx >> 13;
        const unsigned* src = (reg < 2) ? (const unsigned*)g_rwh : (const unsigned*)g_rwl;
        int col = kt * 8 + (l & 3) + (reg & 1) * 4;
        sWf[idx] = src[(size_t)(nt * Hh + h0 + (l >> 2)) * 512 + col];
    }

    const int brow = bt * 16 + grp;
    float creg[4];
    if (kh == 0) {
        float z0 = c0[h0 + tg * 2], z1 = c0[h0 + tg * 2 + 1];
        creg[0] = z0; creg[1] = z1; creg[2] = z0; creg[3] = z1;
        uint2 v;
        v.x = pack2h(creg[0], creg[1]);
        v.y = pack2h(creg[2], creg[3]);
        __stcg((uint2*)&g_ctF[0][((size_t)(bt * 64 + (j >> 1)) * 32 + lane) * 4 + (j & 1) * 2], v);
    }
    __syncthreads();
    grid_barrier(0);

    const size_t GST = (size_t)Tt * Bb * Hh;

    for (int t = 0; t < Tt; ++t) {
        const int p = t & 1;
        const uint4* A = (const uint4*)g_ctF[p];

        float2 Pf0, Pf1, Pi0, Pi1, Po0, Po1;
        float tc0x, tc0y, tc1x, tc1y;
        if (kh == 0) {
            size_t p0 = ((size_t)t * Bb + brow) * Hh + h0 + tg * 2;
            size_t p1 = p0 + 8 * Hh;
            Pf0 = *(const float2*)&g_P[p0];           Pf1 = *(const float2*)&g_P[p1];
            Pi0 = *(const float2*)&g_P[p0 + GST];     Pi1 = *(const float2*)&g_P[p1 + GST];
            Po0 = *(const float2*)&g_P[p0 + 2 * GST]; Po1 = *(const float2*)&g_P[p1 + 2 * GST];
            float2 Pc0 = *(const float2*)&g_P[p0 + 3 * GST], Pc1 = *(const float2*)&g_P[p1 + 3 * GST];
            tc0x = tanhf_fast(Pc0.x); tc0y = tanhf_fast(Pc0.y);
            tc1x = tanhf_fast(Pc1.x); tc1y = tanhf_fast(Pc1.y);
        }

        float acc[3][4];
#pragma unroll
        for (int nt = 0; nt < 3; ++nt) { acc[nt][0] = acc[nt][1] = acc[nt][2] = acc[nt][3] = 0.f; }

#pragma unroll 8
        for (int kt = 0; kt < 32; ++kt) {
            uint4 av = __ldcg(&A[(size_t)(bt * 64 + kth + kt) * 32 + lane]);
#pragma unroll
            for (int nt = 0; nt < 3; ++nt) {
                uint4 bb = *(const uint4*)&sWf[((nt * 64 + kth + kt) * 32 + lane) * 4];
                unsigned bh[2] = {bb.x, bb.y};
                unsigned bl[2] = {bb.z, bb.w};
                mma_f16(acc[nt], (const unsigned*)&av, bh);
                mma_f16(acc[nt], (const unsigned*)&av, bl);
            }
        }

        if (kh == 1) {
            float* r = &sRed[(bt * 32 + lane) * RED_STRIDE];
#pragma unroll
            for (int nt = 0; nt < 3; ++nt)
#pragma unroll
                for (int q = 0; q < 4; ++q) r[nt * 4 + q] = acc[nt][q];
        }
        __syncthreads();

        if (kh == 0) {
            const float* r = &sRed[(bt * 32 + lane) * RED_STRIDE];
#pragma unroll
            for (int nt = 0; nt < 3; ++nt)
#pragma unroll
                for (int q = 0; q < 4; ++q) acc[nt][q] += r[nt * 4 + q];

            const int pn = p ^ 1;
            uint2 v;
            float hx[2][2];
#pragma unroll
            for (int e = 0; e < 2; ++e) {
                float2 Pf = e ? Pf1 : Pf0, Pi = e ? Pi1 : Pi0, Po = e ? Po1 : Po0;
                float tcx = e ? tc1x : tc0x, tcy = e ? tc1y : tc0y;
                float f0 = sigf(acc[0][2 * e] + Pf.x);
                float f1 = sigf(acc[0][2 * e + 1] + Pf.y);
                float i0 = sigf(acc[1][2 * e] + Pi.x);
                float i1 = sigf(acc[1][2 * e + 1] + Pi.y);
                float o0 = sigf(acc[2][2 * e] + Po.x);
                float o1 = sigf(acc[2][2 * e + 1] + Po.y);
                float c0n = f0 * creg[2 * e] + i0 * tcx;
                float c1n = f1 * creg[2 * e + 1] + i1 * tcy;
                creg[2 * e] = c0n; creg[2 * e + 1] = c1n;
                unsigned pv = pack2h(c0n, c1n);
                if (e == 0) v.x = pv; else v.y = pv;
                hx[e][0] = o0 * tanhf_fast(c0n);
                hx[e][1] = o1 * tanhf_fast(c1n);
            }
            // publish ct for next step FIRST (critical path), then h outputs
            __stcg((uint2*)&g_ctF[pn][((size_t)(bt * 64 + (j >> 1)) * 32 + lane) * 4 + (j & 1) * 2], v);
#pragma unroll
            for (int e = 0; e < 2; ++e) {
                int b = brow + 8 * e;
                float2 hv2 = make_float2(hx[e][0], hx[e][1]);
                *(float2*)&out_h[((size_t)b * Tt + t) * Hh + h0 + tg * 2] = hv2;
                if (out_last != nullptr && t == Tt - 1) {
                    *(float2*)&out_last[(size_t)b * Hh + h0 + tg * 2] = hv2;
                }
            }
        }
        grid_barrier(t + 1);
    }
}

// ---------------- launch ----------------------------------------------------
extern "C" void kernel_launch(void* const* d_in, const int* in_sizes, int n_in,
                              void* d_out, int out_size) {
    const float* x   = (const float*)d_in[0];
    const float* Wxf = (const float*)d_in[1];
    const float* Wcf = (const float*)d_in[2];
    const float* bcf = (const float*)d_in[3];
    const float* Wxi = (const float*)d_in[4];
    const float* Wci = (const float*)d_in[5];
    const float* bci = (const float*)d_in[6];
    const float* Wxo = (const float*)d_in[7];
    const float* Wco = (const float*)d_in[8];
    const float* bco = (const float*)d_in[9];
    const float* Wxc = (const float*)d_in[10];
    const float* bxc = (const float*)d_in[11];
    const float* c0  = (const float*)d_in[12];
    float* out = (float*)d_out;

    const long long hid_elems = (long long)Bb * Tt * Hh;
    float* out_last = ((long long)out_size >= hid_elems + (long long)Bb * Hh)
                          ? out + hid_elems : nullptr;

    const int proj_smem = 3 * PSTAGE;                            // 92,160 B
    const int rec_smem  = 24576 * 4 + 4 * 32 * RED_STRIDE * 4;   // 104,960 B
    cudaFuncSetAttribute(k_proj, cudaFuncAttributeMaxDynamicSharedMemorySize, proj_smem);
    cudaFuncSetAttribute(k_rec,  cudaFuncAttributeMaxDynamicSharedMemorySize, rec_smem);

    // exactly 6 launches (ncu -s 5 -c 1 then captures k_rec)
    k_init<<<1, 640>>>();
    k_split_x<<<2048, 256>>>(x);
    k_split_all<<<dim3(512, 7), 256>>>(Wxf, Wxi, Wxo, Wxc, Wcf, Wci, Wco);
    k_bias<<<4, 256>>>(bcf, bci, bco, bxc);
    k_proj<<<dim3(32, 256), 256, proj_smem>>>();
    k_rec<<<128, 256, rec_smem>>>(c0, out, out_last);
}

// round 17
// speedup vs baseline: 2.4393x; 1.0252x over previous
#include <cuda_runtime.h>
#include <cuda_fp16.h>
#include <cstdint>

// Problem dims
#define Bb  64
#define Tt  512
#define Hh  1024
#define INn 1024
#define BT  32768   // Bb*Tt
#define BH  65536   // Bb*Hh

// ---------------- static device scratch -------------------------------------
__device__ __half  g_x [(size_t)BT * INn];         // x fp16 (64 MB)
__device__ __half  g_w [4ull * Hh * INn];          // proj W fp16 (f,i,o,c)
__device__ __half  g_rw[3ull * Hh * Hh];           // rec W fp16 (f,i,o)
__device__ float   g_bias[4 * Hh];                 // bcf,bci,bco,bxc
__device__ float   g_P[4ull * Tt * Bb * Hh];       // preacts [g][t][b][h] (512 MB)
// ct (fp16) in mma A-fragment layout, double buffered:
// [phase][bt(4)][kt(64)][lane(32)][4 uints: a0..a3]
__device__ unsigned g_ctF[2][32768];
__device__ unsigned g_bar[640];                    // grid-barrier counters

// ---------------- helpers ----------------
__device__ __forceinline__ float sigf(float v) { return 1.0f / (1.0f + __expf(-v)); }

// fast, inf-safe tanh
__device__ __forceinline__ float tanhf_fast(float x) {
    float ax = fabsf(x);
    float e = __expf(2.0f * ax);        // large ax -> inf -> 2/inf = 0 -> r = 1
    float r = 1.0f - 2.0f / (e + 1.0f);
    return copysignf(r, x);
}

// D += A*B, m16n8k16 row.col, fp16 in / fp32 acc
__device__ __forceinline__ void mma_f16(float c[4], const unsigned a[4], const unsigned b[2]) {
    asm volatile(
        "mma.sync.aligned.m16n8k16.row.col.f32.f16.f16.f32 "
        "{%0,%1,%2,%3},{%4,%5,%6,%7},{%8,%9},{%0,%1,%2,%3};\n"
        : "+f"(c[0]), "+f"(c[1]), "+f"(c[2]), "+f"(c[3])
        : "r"(a[0]), "r"(a[1]), "r"(a[2]), "r"(a[3]), "r"(b[0]), "r"(b[1]));
}

__device__ __forceinline__ void cp16(void* dst, const void* src) {
    unsigned d = (unsigned)__cvta_generic_to_shared(dst);
    asm volatile("cp.async.cg.shared.global [%0], [%1], 16;\n" :: "r"(d), "l"(src));
}
__device__ __forceinline__ void cp_commit() { asm volatile("cp.async.commit_group;\n"); }
__device__ __forceinline__ void cp_wait1()  { asm volatile("cp.async.wait_group 1;\n"); }
__device__ __forceinline__ void cp_wait0()  { asm volatile("cp.async.wait_group 0;\n"); }

__device__ __forceinline__ unsigned pack2h(float a, float b) {
    __half ha = __float2half_rn(a), hb = __float2half_rn(b);
    return (unsigned)__half_as_ushort(ha) | ((unsigned)__half_as_ushort(hb) << 16);
}

__device__ __forceinline__ void grid_barrier(int slot) {
    __syncthreads();
    if (threadIdx.x == 0) {
        __threadfence();
        unsigned n = gridDim.x;
        if (atomicAdd(&g_bar[slot], 1u) + 1u < n) {
            while (*(volatile unsigned*)&g_bar[slot] < n) { }
        }
        __threadfence();
    }
    __syncthreads();
}

// ---------------- setup kernels ----------------
__global__ void k_split_x(const float* __restrict__ x) {
    const size_t n4 = (size_t)BT * INn / 4;
    const size_t stride = (size_t)gridDim.x * blockDim.x;
    for (size_t i = (size_t)blockIdx.x * blockDim.x + threadIdx.x; i < n4; i += stride) {
        float4 v = ((const float4*)x)[i];
        ushort4 o;
        o.x = __half_as_ushort(__float2half_rn(v.x));
        o.y = __half_as_ushort(__float2half_rn(v.y));
        o.z = __half_as_ushort(__float2half_rn(v.z));
        o.w = __half_as_ushort(__float2half_rn(v.w));
        ((ushort4*)g_x)[i] = o;
    }
}

// Fused prep: y=0..6 -> fp16 convert of 7 weight matrices, y=7 -> bias + barrier init.
__global__ void k_prep(const float* s0, const float* s1, const float* s2,
                       const float* s3, const float* s4, const float* s5,
                       const float* s6,
                       const float* bf, const float* bi, const float* bo,
                       const float* bc) {
    const int y = blockIdx.y;
    if (y == 7) {
        int gidx = blockIdx.x * blockDim.x + threadIdx.x;
        if (gidx < 640) g_bar[gidx] = 0u;
        if (gidx < Hh) {
            g_bias[gidx]          = bf[gidx];
            g_bias[Hh + gidx]     = bi[gidx];
            g_bias[2 * Hh + gidx] = bo[gidx];
            g_bias[3 * Hh + gidx] = bc[gidx];
        }
        return;
    }
    const float* srcs[7] = {s0, s1, s2, s3, s4, s5, s6};
    const float* __restrict__ src = srcs[y];
    __half* dst = (y < 4) ? (g_w + (size_t)y * Hh * INn)
                          : (g_rw + (size_t)(y - 4) * Hh * Hh);
    const size_t n4 = (size_t)Hh * INn / 4;
    const size_t stride = (size_t)gridDim.x * blockDim.x;
    for (size_t i = (size_t)blockIdx.x * blockDim.x + threadIdx.x; i < n4; i += stride) {
        float4 v = ((const float4*)src)[i];
        ushort4 o;
        o.x = __half_as_ushort(__float2half_rn(v.x));
        o.y = __half_as_ushort(__float2half_rn(v.y));
        o.z = __half_as_ushort(__float2half_rn(v.z));
        o.w = __half_as_ushort(__float2half_rn(v.w));
        ((ushort4*)dst)[i] = o;
    }
}

// ---------------- projection GEMM: P = x @ Wx^T + bias (plain fp16) ---------
// C tile 128x128, 8 warps (2x4), warp tile 64x32, K-chunk 32 halves.
// Stage (20,480 B): A(x) | B(w), each 128 rows x 80 B (40-half pad). 3 stages.
#define PARR   10240
#define PSTAGE (2 * PARR)

__global__ void __launch_bounds__(256) k_proj() {
    extern __shared__ char dsm[];
    const int bn = blockIdx.x;              // 0..31  N tiles (fastest -> x reuse in L2)
    const int bm = blockIdx.y;              // 0..255 M tiles
    const int tid = threadIdx.x;
    const int wid = tid >> 5, lane = tid & 31;
    const int wm = wid >> 2, wn = wid & 3;
    const int grp = lane >> 2, tg = lane & 3;

    float acc[4][4][4];
#pragma unroll
    for (int mt = 0; mt < 4; ++mt)
#pragma unroll
        for (int nt = 0; nt < 4; ++nt)
#pragma unroll
            for (int r = 0; r < 4; ++r) acc[mt][nt][r] = 0.f;

    // load one K-chunk (32 halves) into stage kc%3: 2 arrays x 128 rows x 64 B
    auto issue = [&](int kc) {
        char* st = dsm + (kc % 3) * PSTAGE;
#pragma unroll
        for (int i = 0; i < 4; ++i) {
            int flat = tid + i * 256;            // 0..1023
            int arr = flat >> 9;                 // 0..1
            int rem = flat & 511;
            int row = rem >> 2, c16 = rem & 3;   // row 0..127, 16B-chunk 0..3
            char* dst = st + arr * PARR + row * 80 + c16 * 16;
            const __half* src = (arr == 0)
                ? g_x + (size_t)(bm * 128 + row) * 1024 + kc * 32 + c16 * 8
                : g_w + (size_t)(bn * 128 + row) * 1024 + kc * 32 + c16 * 8;
            cp16(dst, src);
        }
        cp_commit();
    };

    issue(0);
    issue(1);

    for (int kc = 0; kc < 32; ++kc) {
        if (kc < 31) cp_wait1(); else cp_wait0();
        __syncthreads();
        if (kc + 2 < 32) issue(kc + 2);

        const char* st = dsm + (kc % 3) * PSTAGE;
        const __half* sA = (const __half*)(st);
        const __half* sB = (const __half*)(st + PARR);

#pragma unroll
        for (int kk = 0; kk < 2; ++kk) {
            unsigned a[4][4], b[4][2];
            const int c0 = kk * 16 + tg * 2;
#pragma unroll
            for (int mt = 0; mt < 4; ++mt) {
                int r0 = wm * 64 + mt * 16 + grp;
                a[mt][0] = *(const unsigned*)&sA[r0 * 40 + c0];
                a[mt][1] = *(const unsigned*)&sA[(r0 + 8) * 40 + c0];
                a[mt][2] = *(const unsigned*)&sA[r0 * 40 + c0 + 8];
                a[mt][3] = *(const unsigned*)&sA[(r0 + 8) * 40 + c0 + 8];
            }
#pragma unroll
            for (int nt = 0; nt < 4; ++nt) {
                int br = wn * 32 + nt * 8 + grp;
                b[nt][0] = *(const unsigned*)&sB[br * 40 + c0];
                b[nt][1] = *(const unsigned*)&sB[br * 40 + c0 + 8];
            }
#pragma unroll
            for (int mt = 0; mt < 4; ++mt)
#pragma unroll
                for (int nt = 0; nt < 4; ++nt)
                    mma_f16(acc[mt][nt], a[mt], b[nt]);
        }
        __syncthreads();
    }

    // epilogue: scatter into [gate][t][b][h] (+bias)
#pragma unroll
    for (int mt = 0; mt < 4; ++mt) {
#pragma unroll
        for (int nt = 0; nt < 4; ++nt) {
            int m0 = bm * 128 + wm * 64 + mt * 16 + grp;
            int n0 = bn * 128 + wn * 32 + nt * 8 + tg * 2;
            int g = n0 >> 10, h = n0 & 1023;
            float b0 = g_bias[n0], b1 = g_bias[n0 + 1];
#pragma unroll
            for (int e = 0; e < 2; ++e) {
                int m = m0 + 8 * e;
                int b = m >> 9, t = m & 511;
                size_t idx = (((size_t)g * Tt + t) * Bb + b) * Hh + h;
                float2 v;
                v.x = acc[mt][nt][2 * e] + b0;
                v.y = acc[mt][nt][2 * e + 1] + b1;
                *(float2*)&g_P[idx] = v;
            }
        }
    }
}

// ---------------- persistent recurrence kernel ------------------------------
// 128 CTAs x 256 threads. CTA j owns h in [8j,8j+8), gates f,i,o (N=3x8).
// Warp = (bt 0..3, khalf 0..1). khalf0: kt 0..31, khalf1: kt 32..63.
// Partials reduced through smem; khalf0 warps do the elementwise update.
// ct: fp32 in regs; fp16 copy in A-frag layout in L2 (double buffered).
#define RED_STRIDE 13
__global__ void __launch_bounds__(256) k_rec(const float* __restrict__ c0,
                                             float* __restrict__ out_h,
                                             float* __restrict__ out_last) {
    extern __shared__ __align__(16) unsigned sWf[];   // [nt(3)][kt(64)][lane(32)][2: b0,b1]
    float* sRed = (float*)(sWf + 12288);              // [4][32][RED_STRIDE]

    const int j = blockIdx.x;
    const int tid = threadIdx.x, wid = tid >> 5, lane = tid & 31;
    const int grp = lane >> 2, tg = lane & 3;
    const int bt = wid & 3;                // batch-tile
    const int kh = wid >> 2;               // k-half
    const int kth = kh * 32;
    const int h0 = j * 8;

    // one-time: rec weights into B-frag layout (fp16)
    for (int idx = tid; idx < 12288; idx += 256) {
        int reg = idx & 1, l = (idx >> 1) & 31, kt = (idx >> 6) & 63, nt = idx >> 12;
        int col = kt * 8 + (l & 3) + reg * 4;
        sWf[idx] = ((const unsigned*)g_rw)[(size_t)(nt * Hh + h0 + (l >> 2)) * 512 + col];
    }

    const int brow = bt * 16 + grp;
    float creg[4];
    if (kh == 0) {
        float z0 = c0[h0 + tg * 2], z1 = c0[h0 + tg * 2 + 1];
        creg[0] = z0; creg[1] = z1; creg[2] = z0; creg[3] = z1;
        uint2 v;
        v.x = pack2h(creg[0], creg[1]);
        v.y = pack2h(creg[2], creg[3]);
        __stcg((uint2*)&g_ctF[0][((size_t)(bt * 64 + (j >> 1)) * 32 + lane) * 4 + (j & 1) * 2], v);
    }
    __syncthreads();
    grid_barrier(0);

    const size_t GST = (size_t)Tt * Bb * Hh;

    for (int t = 0; t < Tt; ++t) {
        const int p = t & 1;
        const uint4* A = (const uint4*)g_ctF[p];

        float2 Pf0, Pf1, Pi0, Pi1, Po0, Po1;
        float tc0x, tc0y, tc1x, tc1y;
        if (kh == 0) {
            size_t p0 = ((size_t)t * Bb + brow) * Hh + h0 + tg * 2;
            size_t p1 = p0 + 8 * Hh;
            Pf0 = *(const float2*)&g_P[p0];           Pf1 = *(const float2*)&g_P[p1];
            Pi0 = *(const float2*)&g_P[p0 + GST];     Pi1 = *(const float2*)&g_P[p1 + GST];
            Po0 = *(const float2*)&g_P[p0 + 2 * GST]; Po1 = *(const float2*)&g_P[p1 + 2 * GST];
            float2 Pc0 = *(const float2*)&g_P[p0 + 3 * GST], Pc1 = *(const float2*)&g_P[p1 + 3 * GST];
            tc0x = tanhf_fast(Pc0.x); tc0y = tanhf_fast(Pc0.y);
            tc1x = tanhf_fast(Pc1.x); tc1y = tanhf_fast(Pc1.y);
        }

        float acc[3][4];
#pragma unroll
        for (int nt = 0; nt < 3; ++nt) { acc[nt][0] = acc[nt][1] = acc[nt][2] = acc[nt][3] = 0.f; }

#pragma unroll 8
        for (int kt = 0; kt < 32; ++kt) {
            uint4 av = __ldcg(&A[(size_t)(bt * 64 + kth + kt) * 32 + lane]);
#pragma unroll
            for (int nt = 0; nt < 3; ++nt) {
                uint2 bb = *(const uint2*)&sWf[((nt * 64 + kth + kt) * 32 + lane) * 2];
                unsigned br[2] = {bb.x, bb.y};
                mma_f16(acc[nt], (const unsigned*)&av, br);
            }
        }

        if (kh == 1) {
            float* r = &sRed[(bt * 32 + lane) * RED_STRIDE];
#pragma unroll
            for (int nt = 0; nt < 3; ++nt)
#pragma unroll
                for (int q = 0; q < 4; ++q) r[nt * 4 + q] = acc[nt][q];
        }
        __syncthreads();

        if (kh == 0) {
            const float* r = &sRed[(bt * 32 + lane) * RED_STRIDE];
#pragma unroll
            for (int nt = 0; nt < 3; ++nt)
#pragma unroll
                for (int q = 0; q < 4; ++q) acc[nt][q] += r[nt * 4 + q];

            const int pn = p ^ 1;
            uint2 v;
            float hx[2][2];
#pragma unroll
            for (int e = 0; e < 2; ++e) {
                float2 Pf = e ? Pf1 : Pf0, Pi = e ? Pi1 : Pi0, Po = e ? Po1 : Po0;
                float tcx = e ? tc1x : tc0x, tcy = e ? tc1y : tc0y;
                float f0 = sigf(acc[0][2 * e] + Pf.x);
                float f1 = sigf(acc[0][2 * e + 1] + Pf.y);
                float i0 = sigf(acc[1][2 * e] + Pi.x);
                float i1 = sigf(acc[1][2 * e + 1] + Pi.y);
                float o0 = sigf(acc[2][2 * e] + Po.x);
                float o1 = sigf(acc[2][2 * e + 1] + Po.y);
                float c0n = f0 * creg[2 * e] + i0 * tcx;
                float c1n = f1 * creg[2 * e + 1] + i1 * tcy;
                creg[2 * e] = c0n; creg[2 * e + 1] = c1n;
                unsigned pv = pack2h(c0n, c1n);
                if (e == 0) v.x = pv; else v.y = pv;
                hx[e][0] = o0 * tanhf_fast(c0n);
                hx[e][1] = o1 * tanhf_fast(c1n);
            }
            // publish ct for next step FIRST (critical path), then h outputs
            __stcg((uint2*)&g_ctF[pn][((size_t)(bt * 64 + (j >> 1)) * 32 + lane) * 4 + (j & 1) * 2], v);
#pragma unroll
            for (int e = 0; e < 2; ++e) {
                int b = brow + 8 * e;
                float2 hv2 = make_float2(hx[e][0], hx[e][1]);
                *(float2*)&out_h[((size_t)b * Tt + t) * Hh + h0 + tg * 2] = hv2;
                if (out_last != nullptr && t == Tt - 1) {
                    *(float2*)&out_last[(size_t)b * Hh + h0 + tg * 2] = hv2;
                }
            }
        }
        grid_barrier(t + 1);
    }
}

// ---------------- launch ----------------------------------------------------
extern "C" void kernel_launch(void* const* d_in, const int* in_sizes, int n_in,
                              void* d_out, int out_size) {
    const float* x   = (const float*)d_in[0];
    const float* Wxf = (const float*)d_in[1];
    const float* Wcf = (const float*)d_in[2];
    const float* bcf = (const float*)d_in[3];
    const float* Wxi = (const float*)d_in[4];
    const float* Wci = (const float*)d_in[5];
    const float* bci = (const float*)d_in[6];
    const float* Wxo = (const float*)d_in[7];
    const float* Wco = (const float*)d_in[8];
    const float* bco = (const float*)d_in[9];
    const float* Wxc = (const float*)d_in[10];
    const float* bxc = (const float*)d_in[11];
    const float* c0  = (const float*)d_in[12];
    float* out = (float*)d_out;

    const long long hid_elems = (long long)Bb * Tt * Hh;
    float* out_last = ((long long)out_size >= hid_elems + (long long)Bb * Hh)
                          ? out + hid_elems : nullptr;

    const int proj_smem = 3 * PSTAGE;                            // 61,440 B
    const int rec_smem  = 12288 * 4 + 4 * 32 * RED_STRIDE * 4;   // 55,808 B
    cudaFuncSetAttribute(k_proj, cudaFuncAttributeMaxDynamicSharedMemorySize, proj_smem);
    cudaFuncSetAttribute(k_rec,  cudaFuncAttributeMaxDynamicSharedMemorySize, rec_smem);

    // 4 launches/call (ncu -s 5 -c 1 should land on k_rec given observed offset)
    k_split_x<<<2048, 256>>>(x);
    k_prep<<<dim3(512, 8), 256>>>(Wxf, Wxi, Wxo, Wxc, Wcf, Wci, Wco,
                                  bcf, bci, bco, bxc);
    k_proj<<<dim3(32, 256), 256, proj_smem>>>();
    k_rec<<<128, 256, rec_smem>>>(c0, out, out_last);
}